// round 1
// baseline (speedup 1.0000x reference)
#include <cuda_runtime.h>

// ---------------- problem constants ----------------
#define NP 50000
#define NTOP 256
#define BATCH 1024
#define NTOT (NP * NTOP)          // 12,800,000
#define HALF_X (NTOT / 2)         // 6,400,000
#define BT (BATCH * NTOP)         // 262,144
#define HALF_I (BT / 2)           // 131,072
#define K1_BLOCKS (HALF_X / 256)  // 25,000
#define K3_BLOCKS (HALF_I / 256)  // 512

// GEMM tiling
#define BBM 128
#define BBN 128
#define KC 16
#define NTILES 391                // ceil(50000/128)

// ---------------- scratch (static device globals; no allocation) ----------------
__device__ float g_X[NTOT];                 // x sample -> overwritten with p
__device__ float g_Pi[BT];                  // xi sample -> overwritten with pi
__device__ float g_sv[NP];
__device__ float g_rv[NP];                  // 1/(1-sv)
__device__ float g_su[BATCH];
__device__ float g_ru[BATCH];
__device__ float g_partial[BATCH * NTILES]; // per (b, ntile) sum of exp(d)
__device__ float g_dj[BATCH];
__device__ float g_kldb[BATCH];
__device__ float g_rp[K1_BLOCKS];           // analytic KL partials

// ---------------- Threefry-2x32 (exact JAX semantics) ----------------
__host__ __device__ __forceinline__ void tf2x32(unsigned int k0, unsigned int k1,
                                                unsigned int c0, unsigned int c1,
                                                unsigned int& o0, unsigned int& o1) {
  unsigned int ks2 = k0 ^ k1 ^ 0x1BD11BDAu;
  unsigned int x0 = c0 + k0, x1 = c1 + k1;
#define TF_R(d) { x0 += x1; x1 = (x1 << (d)) | (x1 >> (32 - (d))); x1 ^= x0; }
  TF_R(13) TF_R(15) TF_R(26) TF_R(6)   x0 += k1;  x1 += ks2 + 1u;
  TF_R(17) TF_R(29) TF_R(16) TF_R(24)  x0 += ks2; x1 += k0 + 2u;
  TF_R(13) TF_R(15) TF_R(26) TF_R(6)   x0 += k0;  x1 += k1 + 3u;
  TF_R(17) TF_R(29) TF_R(16) TF_R(24)  x0 += k1;  x1 += ks2 + 4u;
  TF_R(13) TF_R(15) TF_R(26) TF_R(6)   x0 += ks2; x1 += k0 + 5u;
#undef TF_R
  o0 = x0; o1 = x1;
}

__device__ __forceinline__ float bits_to_normal(unsigned int bits) {
  // JAX: f = bitcast(bits>>9 | 0x3f800000) - 1 in [0,1);
  //      u = max(lo, f*(1 - lo) + lo) with lo = nextafter(-1,0); (1-lo) rounds to 2.0f
  float f = __uint_as_float((bits >> 9) | 0x3f800000u) - 1.0f;
  float lo = __uint_as_float(0xBF7FFFFFu);  // -0.99999994
  float u = fmaxf(lo, fmaf(f, 2.0f, lo));
  return 1.41421356237f * erfinvf(u);       // sqrt(2) rounds to 0x3FB504F3
}

// ---------------- block reduce (256 threads, deterministic, broadcast) ----------------
__device__ __forceinline__ float blockReduce256(float v, volatile float* sh) {
#pragma unroll
  for (int o = 16; o > 0; o >>= 1) v += __shfl_down_sync(0xffffffffu, v, o);
  int lane = threadIdx.x & 31, w = threadIdx.x >> 5;
  if (lane == 0) sh[w] = v;
  __syncthreads();
  if (w == 0) {
    float r = (lane < 8) ? sh[lane] : 0.f;
#pragma unroll
    for (int o = 4; o > 0; o >>= 1) r += __shfl_down_sync(0xffffffffu, r, o);
    if (lane == 0) sh[8] = r;
  }
  __syncthreads();
  float out = sh[8];
  __syncthreads();
  return out;
}

// ---------------- K1: full embedding sample + analytic KL partials ----------------
__global__ __launch_bounds__(256) void k1_sample_x(const float* __restrict__ mu,
                                                   const float* __restrict__ lv,
                                                   unsigned int kx0, unsigned int kx1) {
  int g = blockIdx.x * 256 + threadIdx.x;   // grid sized exactly HALF_X/256
  unsigned int b0, b1;
  tf2x32(kx0, kx1, (unsigned int)g, (unsigned int)(g + HALF_X), b0, b1);
  float local = 0.f;
  {
    float m = mu[g], l = lv[g];
    g_X[g] = fmaf(bits_to_normal(b0), expf(0.5f * l), m);
    local += 1.0f + l - m * m - expf(l);
  }
  {
    int f = g + HALF_X;
    float m = mu[f], l = lv[f];
    g_X[f] = fmaf(bits_to_normal(b1), expf(0.5f * l), m);
    local += 1.0f + l - m * m - expf(l);
  }
  __shared__ float sh[16];
  float s = blockReduce256(local, sh);
  if (threadIdx.x == 0) g_rp[blockIdx.x] = s;
}

// ---------------- K3: batch sample with gather ----------------
__global__ __launch_bounds__(256) void k3_sample_xi(const float* __restrict__ mu,
                                                    const float* __restrict__ lv,
                                                    const int* __restrict__ iidx,
                                                    unsigned int ki0, unsigned int ki1) {
  int g = blockIdx.x * 256 + threadIdx.x;
  unsigned int b0, b1;
  tf2x32(ki0, ki1, (unsigned int)g, (unsigned int)(g + HALF_I), b0, b1);
#pragma unroll
  for (int h = 0; h < 2; h++) {
    int f = g + h * HALF_I;
    unsigned int bits = h ? b1 : b0;
    int row = f >> 8, col = f & 255;
    int a = iidx[row] * NTOP + col;
    float m = mu[a], l = lv[a];
    g_Pi[f] = fmaf(bits_to_normal(bits), expf(0.5f * l), m);
  }
}

// ---------------- K2/K4: double Poincare transform, in place ----------------
__global__ __launch_bounds__(256) void k_transform(int is_batch) {
  float* X = is_batch ? g_Pi : g_X;
  float* svout = is_batch ? g_su : g_sv;
  float* rvout = is_batch ? g_ru : g_rv;
  int row = blockIdx.x;
  int t = threadIdx.x;
  __shared__ float sh[16];
  float x = X[row * NTOP + t];
  float sx = blockReduce256(x * x, sh);
  float s1 = 1.f + sqrtf(1.f + sx);
  float y = x / s1;
  float sy = blockReduce256(y * y, sh);
  float s2 = 1.f + sqrtf(1.f + sy);
  float p = y / s2;
  X[row * NTOP + t] = p;
  float sp = blockReduce256(p * p, sh);
  if (t == 0) {
    float sv = fminf(fmaxf(sp, 0.f), 1.f - 1e-5f);
    svout[row] = sv;
    rvout[row] = 1.f / (1.f - sv);
  }
}

// ---------------- K5: fused GEMM + exp(d) partial sums ----------------
// exp(arccosh(x)) = x + sqrt(x^2-1): no exp/log in the hot loop.
__global__ __launch_bounds__(256) void k5_gemm() {
  __shared__ float As[KC][BBM + 2];   // stride 130: conflict-free transpose stores
  __shared__ float Bs[KC][BBN + 2];
  __shared__ float red[BBM][17];

  int nt = blockIdx.x;          // 0..390
  int bt = blockIdx.y;          // 0..7
  int b0 = bt * BBM, n0 = nt * BBN;
  int t = threadIdx.x;
  int tx = t & 15, ty = t >> 4;

  int lrow0 = t >> 2;           // 0..63
  int lk = (t & 3) << 2;        // 0,4,8,12

  float4 a_reg[2], b_reg[2];
#pragma unroll
  for (int q = 0; q < 2; q++) {
    int row = lrow0 + q * 64;
    a_reg[q] = *(const float4*)&g_Pi[(b0 + row) * NTOP + lk];
    int n = n0 + row;
    b_reg[q] = (n < NP) ? *(const float4*)&g_X[n * NTOP + lk]
                        : make_float4(0.f, 0.f, 0.f, 0.f);
  }

  float acc[8][8];
#pragma unroll
  for (int i = 0; i < 8; i++)
#pragma unroll
    for (int j = 0; j < 8; j++) acc[i][j] = 0.f;

  for (int c = 0; c < NTOP / KC; c++) {
    __syncthreads();
#pragma unroll
    for (int q = 0; q < 2; q++) {
      int row = lrow0 + q * 64;
      As[lk + 0][row] = a_reg[q].x;  As[lk + 1][row] = a_reg[q].y;
      As[lk + 2][row] = a_reg[q].z;  As[lk + 3][row] = a_reg[q].w;
      Bs[lk + 0][row] = b_reg[q].x;  Bs[lk + 1][row] = b_reg[q].y;
      Bs[lk + 2][row] = b_reg[q].z;  Bs[lk + 3][row] = b_reg[q].w;
    }
    __syncthreads();
    if (c + 1 < NTOP / KC) {
      int k0 = (c + 1) * KC;
#pragma unroll
      for (int q = 0; q < 2; q++) {
        int row = lrow0 + q * 64;
        a_reg[q] = *(const float4*)&g_Pi[(b0 + row) * NTOP + k0 + lk];
        int n = n0 + row;
        b_reg[q] = (n < NP) ? *(const float4*)&g_X[n * NTOP + k0 + lk]
                            : make_float4(0.f, 0.f, 0.f, 0.f);
      }
    }
#pragma unroll
    for (int k = 0; k < KC; k++) {
      float av[8], bv[8];
#pragma unroll
      for (int i = 0; i < 8; i++) av[i] = As[k][ty + 16 * i];
#pragma unroll
      for (int j = 0; j < 8; j++) bv[j] = Bs[k][tx + 16 * j];
#pragma unroll
      for (int i = 0; i < 8; i++)
#pragma unroll
        for (int j = 0; j < 8; j++) acc[i][j] = fmaf(av[i], bv[j], acc[i][j]);
    }
  }

  // epilogue: e = x + sqrt(x^2 - 1), masked past N
  float svn[8], rvn[8];
  bool valid[8];
#pragma unroll
  for (int j = 0; j < 8; j++) {
    int n = n0 + tx + 16 * j;
    valid[j] = (n < NP);
    svn[j] = valid[j] ? g_sv[n] : 0.f;
    rvn[j] = valid[j] ? g_rv[n] : 0.f;
  }
  float rowsum[8];
#pragma unroll
  for (int i = 0; i < 8; i++) {
    int rb = b0 + ty + 16 * i;
    float sub = g_su[rb], rub = g_ru[rb];
    float rs = 0.f;
#pragma unroll
    for (int j = 0; j < 8; j++) {
      if (valid[j]) {
        float sq = fmaxf(sub + svn[j] - 2.f * acc[i][j], 0.f);
        float xx = fmaf(2.f * sq, rub * rvn[j], 1.f);
        xx = fmaxf(xx, 1.0f + 1e-7f);
        rs += xx + sqrtf(fmaf(xx, xx, -1.f));
      }
    }
    rowsum[i] = rs;
  }
#pragma unroll
  for (int i = 0; i < 8; i++) red[ty + 16 * i][tx] = rowsum[i];
  __syncthreads();
  if (t < BBM) {
    float s = 0.f;
#pragma unroll
    for (int q = 0; q < 16; q++) s += red[t][q];
    g_partial[(b0 + t) * NTILES + nt] = s;   // unique slot: deterministic
  }
}

// ---------------- K7: d[b, j[b]] ----------------
__global__ void k7_dj(const int* __restrict__ jidx) {
  int b = blockIdx.x;
  int lane = threadIdx.x;
  int jb = jidx[b];
  float dot = 0.f;
  for (int k = lane; k < NTOP; k += 32) dot += g_Pi[b * NTOP + k] * g_X[jb * NTOP + k];
#pragma unroll
  for (int o = 16; o > 0; o >>= 1) dot += __shfl_down_sync(0xffffffffu, dot, o);
  if (lane == 0) {
    float sq = fmaxf(g_su[b] + g_sv[jb] - 2.f * dot, 0.f);
    float xx = fmaf(2.f * sq, g_ru[b] * g_rv[jb], 1.f);
    xx = fmaxf(xx, 1.0f + 1e-7f);
    g_dj[b] = logf(xx + sqrtf(fmaf(xx, xx, -1.f)));
  }
}

// ---------------- K6: per-row logsumexp finish + kld term ----------------
__global__ __launch_bounds__(256) void k6_lse(const float* __restrict__ pij) {
  int b = blockIdx.x, t = threadIdx.x;
  float s = 0.f;
  for (int q = t; q < NTILES; q += 256) s += g_partial[b * NTILES + q];
  __shared__ float sh[256];
  sh[t] = s; __syncthreads();
  for (int w = 128; w > 0; w >>= 1) { if (t < w) sh[t] += sh[t + w]; __syncthreads(); }
  if (t == 0) {
    float L = logf(sh[0]);
    float pb = pij[b];
    g_kldb[b] = pb * (logf(pb) - (g_dj[b] - L));
  }
}

// ---------------- K8: final scalar combine ----------------
__global__ __launch_bounds__(256) void k8_final(float* __restrict__ out) {
  int t = threadIdx.x;
  __shared__ double shd[256];
  double s1 = 0.0;
  for (int b = t; b < BATCH; b += 256) s1 += (double)g_kldb[b];
  double s2 = 0.0;
  for (int q = t; q < K1_BLOCKS; q += 256) s2 += (double)g_rp[q];
  shd[t] = s1; __syncthreads();
  for (int w = 128; w > 0; w >>= 1) { if (t < w) shd[t] += shd[t + w]; __syncthreads(); }
  double kldsum = shd[0];
  __syncthreads();
  shd[t] = s2; __syncthreads();
  for (int w = 128; w > 0; w >>= 1) { if (t < w) shd[t] += shd[t + w]; __syncthreads(); }
  if (t == 0) {
    double frac = 1024.0 / (50000.0 * 50000.0);
    out[0] = (float)(kldsum + (-0.5 * shd[0]) * frac);
  }
}

// ---------------- host launcher ----------------
extern "C" void kernel_launch(void* const* d_in, const int* in_sizes, int n_in,
                              void* d_out, int out_size) {
  const float* pij = (const float*)d_in[0];
  const float* mu  = (const float*)d_in[1];
  const float* lv  = (const float*)d_in[2];
  const int*   ii  = (const int*)d_in[3];
  const int*   jj  = (const int*)d_in[4];
  float* out = (float*)d_out;

  // key(42) = (0,42); split -> kx = (w0(0,2), w0(1,3)), ki = (w1(0,2), w1(1,3))
  unsigned int A0, B0, A1, B1;
  tf2x32(0u, 42u, 0u, 2u, A0, B0);
  tf2x32(0u, 42u, 1u, 3u, A1, B1);

  k1_sample_x<<<K1_BLOCKS, 256>>>(mu, lv, A0, A1);
  k3_sample_xi<<<K3_BLOCKS, 256>>>(mu, lv, ii, B0, B1);
  k_transform<<<NP, 256>>>(0);
  k_transform<<<BATCH, 256>>>(1);
  k5_gemm<<<dim3(NTILES, BATCH / BBM), 256>>>();
  k7_dj<<<BATCH, 32>>>(jj);
  k6_lse<<<BATCH, 256>>>(pij);
  k8_final<<<1, 256>>>(out);
}